// round 6
// baseline (speedup 1.0000x reference)
#include <cuda_runtime.h>
#include <math.h>

#define MAXSPAN 66
#define WSTRIDE 72            // padded x-weight stride (shift<=3 + 66 -> <=72)
#define NRL     1024          // R(256) * 4 levels

struct Params {
    const float* feat[4];
    int H[4];
    int W[4];
    float scale[4];
    int C;
};

// Scratch (allocation-free rule: __device__ globals)
__device__ float              g_wy[NRL * WSTRIDE];
__device__ float              g_wx[NRL * WSTRIDE];   // zero-padded, 4-aligned window
__device__ int4               g_meta[NRL];           // {ny, nx4, base_off, 0}
__device__ unsigned long long g_magic[NRL];          // ceil(2^32/nx4), 64-bit

// Replicates reference `prep` + dense separable-weight accumulation.
__device__ void build_axis(float c1, float c2, int L, float wscale,
                           float* w, int* p_o0, int* p_n) {
    float sz  = fmaxf(__fadd_rn(c2, -c1), 1.0f);
    float bin = __fdiv_rn(sz, 14.0f);
    int   lo_a[28], hi_a[28];
    float fr_a[28];
    bool  va[28];
    int mn = 0x7fffffff, mx = -1;
#pragma unroll
    for (int s = 0; s < 28; s++) {
        float off = (float)(s >> 1) + ((float)(s & 1) + 0.5f) * 0.5f;
        float v   = __fadd_rn(c1, __fmul_rn(off, bin));
        bool valid = (v >= -1.0f) && (v <= (float)L);
        v = fmaxf(v, 0.0f);
        int lo = (int)v;   // floor, v >= 0
        int hi;
        float fr;
        if (lo >= L - 1) { lo = L - 1; hi = L - 1; fr = 0.0f; }
        else             { hi = lo + 1; fr = v - (float)lo; }
        lo_a[s] = lo; hi_a[s] = hi; fr_a[s] = fr; va[s] = valid;
        if (valid) { mn = min(mn, lo); mx = max(mx, hi); }
    }
    if (mx < 0) { *p_o0 = 0; *p_n = 0; return; }
    int n = mx - mn + 1;
    if (n > MAXSPAN) n = MAXSPAN;
    for (int i = 0; i < n; i++) w[i] = 0.0f;
#pragma unroll
    for (int s = 0; s < 28; s++) {
        if (!va[s]) continue;
        int l = lo_a[s] - mn, h = hi_a[s] - mn;
        if (l < n) w[l] += 1.0f - fr_a[s];
        if (h < n) w[h] += fr_a[s];
    }
    for (int i = 0; i < n; i++) w[i] *= wscale;
    *p_o0 = mn; *p_n = n;
}

// Fused prep: one thread per (roi, level). 1024 threads in 8 blocks.
__global__ void prep_fused_kernel(Params p, const float* __restrict__ boxes,
                                  int nrl) {
    const int rl = blockIdx.x * blockDim.x + threadIdx.x;
    if (rl >= nrl) return;
    const int r   = rl >> 2;
    const int lvl = rl & 3;
    const float scale = p.scale[lvl];

    // Y axis -> directly into g_wy
    int y0, ny;
    {
        float y1 = __fmul_rn(boxes[r * 4 + 1], scale);
        float y2 = __fmul_rn(boxes[r * 4 + 3], scale);
        build_axis(y1, y2, p.H[lvl], 1.0f / 28.0f, &g_wy[rl * WSTRIDE], &y0, &ny);
    }
    // X axis -> temp, then zero-pad to 4-aligned window in g_wx
    int x0al, nx4;
    {
        float wtmp[MAXSPAN];
        float x1 = __fmul_rn(boxes[r * 4 + 0], scale);
        float x2 = __fmul_rn(boxes[r * 4 + 2], scale);
        int o0, n;
        build_axis(x1, x2, p.W[lvl], 1.0f / 28.0f, wtmp, &o0, &n);
        x0al      = o0 & ~3;
        int shift = o0 - x0al;
        int nxp   = (shift + n + 3) & ~3;
        float* dst = &g_wx[rl * WSTRIDE];
        for (int j = 0; j < nxp; j++) {
            int k = j - shift;
            dst[j] = (k >= 0 && k < n) ? wtmp[k] : 0.0f;
        }
        nx4 = nxp >> 2;
    }
    g_meta[rl] = make_int4(ny, nx4, y0 * p.W[lvl] + x0al, 0);
    int d = nx4 > 0 ? nx4 : 1;
    g_magic[rl] = (0x100000000ULL + (unsigned long long)d - 1) /
                  (unsigned long long)d;
}

// grid (R*4, 8). 128 threads = 4 warps; channel group = 32 channels;
// each warp: 8 channels in 2 passes of 4. Pixel loop unrolled x2:
// 8 independent LDG.128 in flight per warp-iteration.
__global__ __launch_bounds__(128)
void roi_main_kernel(Params p, const int* __restrict__ bids,
                     float* __restrict__ out) {
    const int rl  = blockIdx.x;
    const int lvl = rl & 3;
    const int r   = rl >> 2;
    const int W   = p.W[lvl];
    const int HW  = p.H[lvl] * W;
    const int C   = p.C;

    __shared__ float  s_wy[MAXSPAN];
    __shared__ float4 s_wx4[WSTRIDE / 4];

    const int4 m = g_meta[rl];
    const int ny = m.x, nx4 = m.y;
    const unsigned long long magic = g_magic[rl];

    const int tid = threadIdx.x;
    for (int i = tid; i < ny; i += 128) s_wy[i] = g_wy[rl * WSTRIDE + i];
    for (int i = tid; i < nx4; i += 128)
        s_wx4[i] = ((const float4*)&g_wx[rl * WSTRIDE])[i];
    __syncthreads();

    const int total = ny * nx4;
    const int b = __ldg(&bids[r]);
    const float* __restrict__ fb = p.feat[lvl] + (size_t)b * C * HW + m.z;

    const int warp = tid >> 5, lane = tid & 31;
    const int cbase = blockIdx.y * 32 + warp * 8;
    const int outbase = r * 4 * C + lvl * C;
    const unsigned W4 = (unsigned)(W >> 2);

#pragma unroll
    for (int k = 0; k < 2; k++) {
        const int c = cbase + k * 4;
        const float4* __restrict__ f0 = (const float4*)(fb + (size_t)c * HW);
        const float4* __restrict__ f1 = (const float4*)(fb + (size_t)(c + 1) * HW);
        const float4* __restrict__ f2 = (const float4*)(fb + (size_t)(c + 2) * HW);
        const float4* __restrict__ f3 = (const float4*)(fb + (size_t)(c + 3) * HW);
        float a0 = 0.f, a1 = 0.f, a2 = 0.f, a3 = 0.f;

        int i = lane;
        // paired iterations: (i, i+32) -> 8 LDG.128 issued back-to-back
        for (; i + 32 < total; i += 64) {
            unsigned iA = (unsigned)i, iB = (unsigned)(i + 32);
            unsigned yA = (unsigned)(((unsigned long long)iA * magic) >> 32);
            unsigned yB = (unsigned)(((unsigned long long)iB * magic) >> 32);
            unsigned xA = iA - yA * (unsigned)nx4;
            unsigned xB = iB - yB * (unsigned)nx4;
            int offA = (int)(yA * W4 + xA);
            int offB = (int)(yB * W4 + xB);
            float4 v0A = __ldg(f0 + offA), v0B = __ldg(f0 + offB);
            float4 v1A = __ldg(f1 + offA), v1B = __ldg(f1 + offB);
            float4 v2A = __ldg(f2 + offA), v2B = __ldg(f2 + offB);
            float4 v3A = __ldg(f3 + offA), v3B = __ldg(f3 + offB);
            float  wyA = s_wy[yA], wyB = s_wy[yB];
            float4 wxA = s_wx4[xA], wxB = s_wx4[xB];
            float4 wA = make_float4(wyA * wxA.x, wyA * wxA.y, wyA * wxA.z, wyA * wxA.w);
            float4 wB = make_float4(wyB * wxB.x, wyB * wxB.y, wyB * wxB.z, wyB * wxB.w);
            a0 = fmaf(wA.x, v0A.x, fmaf(wA.y, v0A.y, fmaf(wA.z, v0A.z, fmaf(wA.w, v0A.w, a0))));
            a0 = fmaf(wB.x, v0B.x, fmaf(wB.y, v0B.y, fmaf(wB.z, v0B.z, fmaf(wB.w, v0B.w, a0))));
            a1 = fmaf(wA.x, v1A.x, fmaf(wA.y, v1A.y, fmaf(wA.z, v1A.z, fmaf(wA.w, v1A.w, a1))));
            a1 = fmaf(wB.x, v1B.x, fmaf(wB.y, v1B.y, fmaf(wB.z, v1B.z, fmaf(wB.w, v1B.w, a1))));
            a2 = fmaf(wA.x, v2A.x, fmaf(wA.y, v2A.y, fmaf(wA.z, v2A.z, fmaf(wA.w, v2A.w, a2))));
            a2 = fmaf(wB.x, v2B.x, fmaf(wB.y, v2B.y, fmaf(wB.z, v2B.z, fmaf(wB.w, v2B.w, a2))));
            a3 = fmaf(wA.x, v3A.x, fmaf(wA.y, v3A.y, fmaf(wA.z, v3A.z, fmaf(wA.w, v3A.w, a3))));
            a3 = fmaf(wB.x, v3B.x, fmaf(wB.y, v3B.y, fmaf(wB.z, v3B.z, fmaf(wB.w, v3B.w, a3))));
        }
        for (; i < total; i += 32) {
            unsigned yy  = (unsigned)(((unsigned long long)(unsigned)i * magic) >> 32);
            unsigned xx4 = (unsigned)i - yy * (unsigned)nx4;
            int off = (int)(yy * W4 + xx4);
            float  wy = s_wy[yy];
            float4 wx = s_wx4[xx4];
            float4 w4 = make_float4(wy * wx.x, wy * wx.y, wy * wx.z, wy * wx.w);
            float4 v0 = __ldg(f0 + off);
            float4 v1 = __ldg(f1 + off);
            float4 v2 = __ldg(f2 + off);
            float4 v3 = __ldg(f3 + off);
            a0 = fmaf(w4.x, v0.x, fmaf(w4.y, v0.y, fmaf(w4.z, v0.z, fmaf(w4.w, v0.w, a0))));
            a1 = fmaf(w4.x, v1.x, fmaf(w4.y, v1.y, fmaf(w4.z, v1.z, fmaf(w4.w, v1.w, a1))));
            a2 = fmaf(w4.x, v2.x, fmaf(w4.y, v2.y, fmaf(w4.z, v2.z, fmaf(w4.w, v2.w, a2))));
            a3 = fmaf(w4.x, v3.x, fmaf(w4.y, v3.y, fmaf(w4.z, v3.z, fmaf(w4.w, v3.w, a3))));
        }
#pragma unroll
        for (int o = 16; o; o >>= 1) {
            a0 += __shfl_xor_sync(0xffffffffu, a0, o);
            a1 += __shfl_xor_sync(0xffffffffu, a1, o);
            a2 += __shfl_xor_sync(0xffffffffu, a2, o);
            a3 += __shfl_xor_sync(0xffffffffu, a3, o);
        }
        if (lane == 0) {
            out[outbase + c + 0] = a0;
            out[outbase + c + 1] = a1;
            out[outbase + c + 2] = a2;
            out[outbase + c + 3] = a3;
        }
    }
}

extern "C" void kernel_launch(void* const* d_in, const int* in_sizes, int n_in,
                              void* d_out, int out_size) {
    const int B = 2, C = 256;
    Params p;
    for (int i = 0; i < 4; i++) {
        p.feat[i] = (const float*)d_in[i];
        long npix = (long)in_sizes[i] / ((long)B * C);
        int Hh = (int)(sqrt((double)npix * 5.0 / 8.0) + 0.5);  // 800:1280 aspect
        int Ww = (int)(npix / Hh);
        p.H[i] = Hh;
        p.W[i] = Ww;
        p.scale[i] = 0.25f / (float)(1 << i);
    }
    p.C = C;
    const int R = in_sizes[4] / 4;
    const float* boxes = (const float*)d_in[4];
    const int*   bids  = (const int*)d_in[5];

    const int nrl = R * 4;
    prep_fused_kernel<<<(nrl + 127) / 128, 128>>>(p, boxes, nrl);
    roi_main_kernel<<<dim3(nrl, 8), 128>>>(p, bids, (float*)d_out);
}

// round 7
// speedup vs baseline: 1.0729x; 1.0729x over previous
#include <cuda_runtime.h>
#include <math.h>

#define MAXSPAN 66

struct Params {
    const float* feat[4];
    int H[4];
    int W[4];
    float scale[4];
    int C;
};

// Single fused kernel. grid (R*4, 8), 128 threads.
// Block prologue: warp0 builds Y weights, warp1 builds X weights (padded to
// 4-aligned window), via per-lane sample scalars + shared-memory gather —
// no local arrays, no spills. Then the R5 float4 pixel loop.
__global__ __launch_bounds__(128, 8)
void roi_fused_kernel(Params p, const float* __restrict__ boxes,
                      const int* __restrict__ bids,
                      float* __restrict__ out) {
    const int rl  = blockIdx.x;
    const int lvl = rl & 3;
    const int r   = rl >> 2;
    const int W   = p.W[lvl];
    const int H   = p.H[lvl];
    const int HW  = H * W;
    const int C   = p.C;

    __shared__ float  s_wy[MAXSPAN];
    __shared__ float4 s_wx4[18];                  // 72 padded x-weights
    __shared__ float  s_wlo[2][32], s_whi[2][32];
    __shared__ int    s_slo[2][32], s_shi[2][32];
    __shared__ int    s_y0, s_ny, s_x0al, s_nx4;
    __shared__ unsigned long long s_magic;

    const int tid  = threadIdx.x;
    const int warp = tid >> 5, lane = tid & 31;

    if (warp < 2) {
        const int axis = warp;                    // 0 = Y, 1 = X
        const float scale = p.scale[lvl];
        const int L = axis ? W : H;
        float c1 = __fmul_rn(boxes[r * 4 + (axis ? 0 : 1)], scale);
        float c2 = __fmul_rn(boxes[r * 4 + (axis ? 2 : 3)], scale);
        float sz  = fmaxf(__fadd_rn(c2, -c1), 1.0f);
        float bin = __fdiv_rn(sz, 14.0f);

        // per-lane sample s = lane (lanes 28..31 inert)
        const int s = lane;
        float off = (float)(s >> 1) + ((float)(s & 1) + 0.5f) * 0.5f;
        float v   = __fadd_rn(c1, __fmul_rn(off, bin));
        bool valid = (s < 28) && (v >= -1.0f) && (v <= (float)L);
        v = fmaxf(v, 0.0f);
        int lo = (int)v;                          // floor, v >= 0
        int hi; float fr;
        if (lo >= L - 1) { lo = L - 1; hi = L - 1; fr = 0.0f; }
        else             { hi = lo + 1; fr = v - (float)lo; }
        s_slo[axis][lane] = lo;
        s_shi[axis][lane] = hi;
        s_wlo[axis][lane] = valid ? (1.0f - fr) : 0.0f;
        s_whi[axis][lane] = valid ? fr : 0.0f;

        int mnv = valid ? lo : 0x7fffffff;
        int mxv = valid ? hi : -1;
#pragma unroll
        for (int o = 16; o; o >>= 1) {
            mnv = min(mnv, __shfl_xor_sync(0xffffffffu, mnv, o));
            mxv = max(mxv, __shfl_xor_sync(0xffffffffu, mxv, o));
        }
        int n = (mxv < 0) ? 0 : (mxv - mnv + 1);
        if (n > MAXSPAN) n = MAXSPAN;
        if (mxv < 0) mnv = 0;
        __syncwarp();

        if (axis == 0) {
            for (int j = lane; j < n; j += 32) {
                int idx = mnv + j;
                float w = 0.0f;
                for (int t = 0; t < 28; t++) {   // matches reference sum order
                    if (s_slo[0][t] == idx) w += s_wlo[0][t];
                    if (s_shi[0][t] == idx) w += s_whi[0][t];
                }
                s_wy[j] = w * (1.0f / 28.0f);
            }
            if (lane == 0) { s_y0 = mnv; s_ny = n; }
        } else {
            int x0al  = mnv & ~3;
            int shift = mnv - x0al;
            int nxp   = (n > 0) ? ((shift + n + 3) & ~3) : 0;
            float* wx = (float*)s_wx4;
            for (int j = lane; j < nxp; j += 32) {
                int k = j - shift;
                float w = 0.0f;
                if (k >= 0 && k < n) {
                    int idx = mnv + k;
                    for (int t = 0; t < 28; t++) {
                        if (s_slo[1][t] == idx) w += s_wlo[1][t];
                        if (s_shi[1][t] == idx) w += s_whi[1][t];
                    }
                }
                wx[j] = w * (1.0f / 28.0f);
            }
            if (lane == 0) {
                int nx4 = nxp >> 2;
                s_x0al = x0al;
                s_nx4  = nx4;
                int d = nx4 > 0 ? nx4 : 1;
                s_magic = (0x100000000ULL + (unsigned long long)d - 1) /
                          (unsigned long long)d;
            }
        }
    }
    __syncthreads();

    const int ny = s_ny, nx4 = s_nx4;
    const unsigned long long magic = s_magic;
    const int total = ny * nx4;
    const int b = __ldg(&bids[r]);
    const float* __restrict__ fb =
        p.feat[lvl] + (size_t)b * C * HW + (s_y0 * W + s_x0al);

    const int cbase = blockIdx.y * 32 + warp * 8;
    const int outbase = r * 4 * C + lvl * C;
    const unsigned W4 = (unsigned)(W >> 2);

#pragma unroll
    for (int k = 0; k < 2; k++) {
        const int c = cbase + k * 4;
        const float4* __restrict__ f0 = (const float4*)(fb + (size_t)c * HW);
        const float4* __restrict__ f1 = (const float4*)(fb + (size_t)(c + 1) * HW);
        const float4* __restrict__ f2 = (const float4*)(fb + (size_t)(c + 2) * HW);
        const float4* __restrict__ f3 = (const float4*)(fb + (size_t)(c + 3) * HW);
        float a0 = 0.f, a1 = 0.f, a2 = 0.f, a3 = 0.f;
        for (int i = lane; i < total; i += 32) {
            unsigned yy  = (unsigned)(((unsigned long long)(unsigned)i * magic) >> 32);
            unsigned xx4 = (unsigned)i - yy * (unsigned)nx4;
            int off = (int)(yy * W4 + xx4);
            float  wy = s_wy[yy];
            float4 wx = s_wx4[xx4];
            float4 w4 = make_float4(wy * wx.x, wy * wx.y, wy * wx.z, wy * wx.w);
            float4 v0 = __ldg(f0 + off);
            float4 v1 = __ldg(f1 + off);
            float4 v2 = __ldg(f2 + off);
            float4 v3 = __ldg(f3 + off);
            a0 = fmaf(w4.x, v0.x, fmaf(w4.y, v0.y, fmaf(w4.z, v0.z, fmaf(w4.w, v0.w, a0))));
            a1 = fmaf(w4.x, v1.x, fmaf(w4.y, v1.y, fmaf(w4.z, v1.z, fmaf(w4.w, v1.w, a1))));
            a2 = fmaf(w4.x, v2.x, fmaf(w4.y, v2.y, fmaf(w4.z, v2.z, fmaf(w4.w, v2.w, a2))));
            a3 = fmaf(w4.x, v3.x, fmaf(w4.y, v3.y, fmaf(w4.z, v3.z, fmaf(w4.w, v3.w, a3))));
        }
#pragma unroll
        for (int o = 16; o; o >>= 1) {
            a0 += __shfl_xor_sync(0xffffffffu, a0, o);
            a1 += __shfl_xor_sync(0xffffffffu, a1, o);
            a2 += __shfl_xor_sync(0xffffffffu, a2, o);
            a3 += __shfl_xor_sync(0xffffffffu, a3, o);
        }
        if (lane == 0) {
            out[outbase + c + 0] = a0;
            out[outbase + c + 1] = a1;
            out[outbase + c + 2] = a2;
            out[outbase + c + 3] = a3;
        }
    }
}

extern "C" void kernel_launch(void* const* d_in, const int* in_sizes, int n_in,
                              void* d_out, int out_size) {
    const int B = 2, C = 256;
    Params p;
    for (int i = 0; i < 4; i++) {
        p.feat[i] = (const float*)d_in[i];
        long npix = (long)in_sizes[i] / ((long)B * C);
        int Hh = (int)(sqrt((double)npix * 5.0 / 8.0) + 0.5);  // 800:1280 aspect
        int Ww = (int)(npix / Hh);
        p.H[i] = Hh;
        p.W[i] = Ww;
        p.scale[i] = 0.25f / (float)(1 << i);
    }
    p.C = C;
    const int R = in_sizes[4] / 4;
    const float* boxes = (const float*)d_in[4];
    const int*   bids  = (const int*)d_in[5];

    roi_fused_kernel<<<dim3(R * 4, 8), 128>>>(p, boxes, bids, (float*)d_out);
}

// round 8
// speedup vs baseline: 1.4874x; 1.3863x over previous
#include <cuda_runtime.h>
#include <math.h>

#define MAXSPAN 66
#define WSTRIDE 72            // padded x-weight stride
#define NRL     1024          // R(256) * 4 levels

struct Params {
    const float* feat[4];
    int H[4];
    int W[4];
    float scale[4];
    int C;
};

// Scratch (allocation-free rule: __device__ globals)
__device__ float              g_wy[NRL * WSTRIDE];
__device__ float              g_wx[NRL * WSTRIDE];   // zero-padded, 4-aligned window
__device__ int4               g_meta[NRL];           // {ny, nx4, base_off, 0}
__device__ unsigned long long g_magic[NRL];          // ceil(2^32/nx4), 64-bit

// Warp-parallel prep: one block per (roi,level); warp0 = Y axis, warp1 = X axis.
// Per-lane sample scalars + shared-memory gather — no local arrays, no spills.
__global__ __launch_bounds__(64)
void prep_kernel(Params p, const float* __restrict__ boxes) {
    const int rl  = blockIdx.x;
    const int r   = rl >> 2;
    const int lvl = rl & 3;

    __shared__ float s_wlo[2][32], s_whi[2][32];
    __shared__ int   s_slo[2][32], s_shi[2][32];
    __shared__ int   sh_y0, sh_ny, sh_x0al, sh_nx4;

    const int warp = threadIdx.x >> 5, lane = threadIdx.x & 31;
    const int axis = warp;                        // 0 = Y, 1 = X
    const float scale = p.scale[lvl];
    const int L = axis ? p.W[lvl] : p.H[lvl];
    float c1 = __fmul_rn(boxes[r * 4 + (axis ? 0 : 1)], scale);
    float c2 = __fmul_rn(boxes[r * 4 + (axis ? 2 : 3)], scale);
    float sz  = fmaxf(__fadd_rn(c2, -c1), 1.0f);
    float bin = __fdiv_rn(sz, 14.0f);

    // per-lane sample s = lane (lanes 28..31 inert)
    const int s = lane;
    float off = (float)(s >> 1) + ((float)(s & 1) + 0.5f) * 0.5f;
    float v   = __fadd_rn(c1, __fmul_rn(off, bin));
    bool valid = (s < 28) && (v >= -1.0f) && (v <= (float)L);
    v = fmaxf(v, 0.0f);
    int lo = (int)v;                              // floor, v >= 0
    int hi; float fr;
    if (lo >= L - 1) { lo = L - 1; hi = L - 1; fr = 0.0f; }
    else             { hi = lo + 1; fr = v - (float)lo; }
    s_slo[axis][lane] = lo;
    s_shi[axis][lane] = hi;
    s_wlo[axis][lane] = valid ? (1.0f - fr) : 0.0f;
    s_whi[axis][lane] = valid ? fr : 0.0f;

    int mnv = valid ? lo : 0x7fffffff;
    int mxv = valid ? hi : -1;
#pragma unroll
    for (int o = 16; o; o >>= 1) {
        mnv = min(mnv, __shfl_xor_sync(0xffffffffu, mnv, o));
        mxv = max(mxv, __shfl_xor_sync(0xffffffffu, mxv, o));
    }
    int n = (mxv < 0) ? 0 : (mxv - mnv + 1);
    if (n > MAXSPAN) n = MAXSPAN;
    if (mxv < 0) mnv = 0;
    __syncwarp();

    if (axis == 0) {
        float* wy = &g_wy[rl * WSTRIDE];
        for (int j = lane; j < n; j += 32) {
            int idx = mnv + j;
            float w = 0.0f;
            for (int t = 0; t < 28; t++) {        // matches reference sum order
                if (s_slo[0][t] == idx) w += s_wlo[0][t];
                if (s_shi[0][t] == idx) w += s_whi[0][t];
            }
            wy[j] = w * (1.0f / 28.0f);
        }
        if (lane == 0) { sh_y0 = mnv; sh_ny = n; }
    } else {
        int x0al  = mnv & ~3;
        int shift = mnv - x0al;
        int nxp   = (n > 0) ? ((shift + n + 3) & ~3) : 0;
        float* wx = &g_wx[rl * WSTRIDE];
        for (int j = lane; j < nxp; j += 32) {
            int k = j - shift;
            float w = 0.0f;
            if (k >= 0 && k < n) {
                int idx = mnv + k;
                for (int t = 0; t < 28; t++) {
                    if (s_slo[1][t] == idx) w += s_wlo[1][t];
                    if (s_shi[1][t] == idx) w += s_whi[1][t];
                }
            }
            wx[j] = w * (1.0f / 28.0f);
        }
        if (lane == 0) { sh_x0al = x0al; sh_nx4 = nxp >> 2; }
    }
    __syncthreads();
    if (threadIdx.x == 0) {
        int ny  = sh_ny;
        int nx4 = sh_nx4;
        g_meta[rl] = make_int4(ny, nx4, sh_y0 * p.W[lvl] + sh_x0al, 0);
        int d = nx4 > 0 ? nx4 : 1;
        g_magic[rl] = (0x100000000ULL + (unsigned long long)d - 1) /
                      (unsigned long long)d;
    }
}

// grid (R*4, 8). 128 threads = 4 warps; channel group = 32 channels;
// each warp: 8 channels in 2 passes of 4, float4 loads per pixel-quad.
__global__ __launch_bounds__(128, 8)
void roi_main_kernel(Params p, const int* __restrict__ bids,
                     float* __restrict__ out) {
    const int rl  = blockIdx.x;
    const int lvl = rl & 3;
    const int r   = rl >> 2;
    const int W   = p.W[lvl];
    const int HW  = p.H[lvl] * W;
    const int C   = p.C;

    __shared__ float  s_wy[MAXSPAN];
    __shared__ float4 s_wx4[WSTRIDE / 4];

    const int4 m = g_meta[rl];
    const int ny = m.x, nx4 = m.y;
    const unsigned long long magic = g_magic[rl];

    const int tid = threadIdx.x;
    for (int i = tid; i < ny; i += 128) s_wy[i] = g_wy[rl * WSTRIDE + i];
    for (int i = tid; i < nx4; i += 128)
        s_wx4[i] = ((const float4*)&g_wx[rl * WSTRIDE])[i];
    __syncthreads();

    const int total = ny * nx4;
    const int b = __ldg(&bids[r]);
    const float* __restrict__ fb = p.feat[lvl] + (size_t)b * C * HW + m.z;

    const int warp = tid >> 5, lane = tid & 31;
    const int cbase = blockIdx.y * 32 + warp * 8;
    const int outbase = r * 4 * C + lvl * C;
    const unsigned W4 = (unsigned)(W >> 2);

#pragma unroll
    for (int k = 0; k < 2; k++) {
        const int c = cbase + k * 4;
        const float4* __restrict__ f0 = (const float4*)(fb + (size_t)c * HW);
        const float4* __restrict__ f1 = (const float4*)(fb + (size_t)(c + 1) * HW);
        const float4* __restrict__ f2 = (const float4*)(fb + (size_t)(c + 2) * HW);
        const float4* __restrict__ f3 = (const float4*)(fb + (size_t)(c + 3) * HW);
        float a0 = 0.f, a1 = 0.f, a2 = 0.f, a3 = 0.f;
        for (int i = lane; i < total; i += 32) {
            unsigned yy  = (unsigned)(((unsigned long long)(unsigned)i * magic) >> 32);
            unsigned xx4 = (unsigned)i - yy * (unsigned)nx4;
            int off = (int)(yy * W4 + xx4);
            float  wy = s_wy[yy];
            float4 wx = s_wx4[xx4];
            float4 w4 = make_float4(wy * wx.x, wy * wx.y, wy * wx.z, wy * wx.w);
            float4 v0 = __ldg(f0 + off);
            float4 v1 = __ldg(f1 + off);
            float4 v2 = __ldg(f2 + off);
            float4 v3 = __ldg(f3 + off);
            a0 = fmaf(w4.x, v0.x, fmaf(w4.y, v0.y, fmaf(w4.z, v0.z, fmaf(w4.w, v0.w, a0))));
            a1 = fmaf(w4.x, v1.x, fmaf(w4.y, v1.y, fmaf(w4.z, v1.z, fmaf(w4.w, v1.w, a1))));
            a2 = fmaf(w4.x, v2.x, fmaf(w4.y, v2.y, fmaf(w4.z, v2.z, fmaf(w4.w, v2.w, a2))));
            a3 = fmaf(w4.x, v3.x, fmaf(w4.y, v3.y, fmaf(w4.z, v3.z, fmaf(w4.w, v3.w, a3))));
        }
#pragma unroll
        for (int o = 16; o; o >>= 1) {
            a0 += __shfl_xor_sync(0xffffffffu, a0, o);
            a1 += __shfl_xor_sync(0xffffffffu, a1, o);
            a2 += __shfl_xor_sync(0xffffffffu, a2, o);
            a3 += __shfl_xor_sync(0xffffffffu, a3, o);
        }
        if (lane == 0) {
            out[outbase + c + 0] = a0;
            out[outbase + c + 1] = a1;
            out[outbase + c + 2] = a2;
            out[outbase + c + 3] = a3;
        }
    }
}

extern "C" void kernel_launch(void* const* d_in, const int* in_sizes, int n_in,
                              void* d_out, int out_size) {
    const int B = 2, C = 256;
    Params p;
    for (int i = 0; i < 4; i++) {
        p.feat[i] = (const float*)d_in[i];
        long npix = (long)in_sizes[i] / ((long)B * C);
        int Hh = (int)(sqrt((double)npix * 5.0 / 8.0) + 0.5);  // 800:1280 aspect
        int Ww = (int)(npix / Hh);
        p.H[i] = Hh;
        p.W[i] = Ww;
        p.scale[i] = 0.25f / (float)(1 << i);
    }
    p.C = C;
    const int R = in_sizes[4] / 4;
    const float* boxes = (const float*)d_in[4];
    const int*   bids  = (const int*)d_in[5];

    prep_kernel<<<R * 4, 64>>>(p, boxes);
    roi_main_kernel<<<dim3(R * 4, 8), 128>>>(p, bids, (float*)d_out);
}